// round 1
// baseline (speedup 1.0000x reference)
#include <cuda_runtime.h>
#include <math.h>

// Problem-shape constants (registry shapes are fixed for this problem id).
#define NN 50000
#define F_DIM 256
#define EE 800000

// ---------------- static device scratch (no allocations allowed) -------------
__device__ float g_buf0[NN * F_DIM];   // GEMM outputs
__device__ float g_buf1[NN * F_DIM];   // activations
__device__ float g_ssrc[NN];
__device__ float g_sdst[NN];
__device__ int   g_cnt[NN];
__device__ int   g_rowptr[NN + 1];
__device__ int   g_fill[NN];
__device__ int   g_srcidx[EE];
__device__ int   g_part[64];
__device__ float g_sum[F_DIM];
__device__ float g_sq[F_DIM];

// ---------------- small utility kernels --------------------------------------
__global__ void k_zero_int(int* p, int n) {
    int i = blockIdx.x * blockDim.x + threadIdx.x;
    if (i < n) p[i] = 0;
}

__global__ void k_zero_stats() {
    int i = threadIdx.x;
    if (i < F_DIM) { g_sum[i] = 0.f; g_sq[i] = 0.f; }
}

__global__ void k_hist(const int* __restrict__ dst, int E, int* __restrict__ cnt) {
    int e = blockIdx.x * blockDim.x + threadIdx.x;
    if (e < E) atomicAdd(&cnt[dst[e]], 1);
}

// Inclusive scan of counts per 1024-chunk; partials out.
__global__ void k_scan1(const int* __restrict__ cnt, int n, int* __restrict__ rowptr,
                        int* __restrict__ part) {
    __shared__ int s[1024];
    int idx = blockIdx.x * 1024 + threadIdx.x;
    int v = (idx < n) ? cnt[idx] : 0;
    s[threadIdx.x] = v;
    __syncthreads();
    for (int off = 1; off < 1024; off <<= 1) {
        int t = 0;
        if (threadIdx.x >= off) t = s[threadIdx.x - off];
        __syncthreads();
        if (threadIdx.x >= off) s[threadIdx.x] += t;
        __syncthreads();
    }
    if (idx < n) rowptr[idx + 1] = s[threadIdx.x];
    if (threadIdx.x == 1023) part[blockIdx.x] = s[1023];
}

__global__ void k_scan2(int* part, int nb) {
    if (threadIdx.x == 0 && blockIdx.x == 0) {
        int acc = 0;
        for (int i = 0; i < nb; i++) { int v = part[i]; part[i] = acc; acc += v; }
    }
}

__global__ void k_scan3(int* __restrict__ rowptr, const int* __restrict__ part, int n) {
    int idx = blockIdx.x * blockDim.x + threadIdx.x;
    if (idx < n) rowptr[idx + 1] += part[idx >> 10];
    if (idx == 0) rowptr[0] = 0;
}

__global__ void k_copyfill(const int* __restrict__ rowptr, int* __restrict__ fill, int n) {
    int i = blockIdx.x * blockDim.x + threadIdx.x;
    if (i < n) fill[i] = rowptr[i];
}

__global__ void k_scatter(const int* __restrict__ src, const int* __restrict__ dst, int E,
                          int* __restrict__ fill, int* __restrict__ srcidx) {
    int e = blockIdx.x * blockDim.x + threadIdx.x;
    if (e < E) {
        int p = atomicAdd(&fill[dst[e]], 1);
        srcidx[p] = src[e];
    }
}

// ---------------- attention scores (warp per node) ----------------------------
__global__ void k_scores(const float* __restrict__ h, const float* __restrict__ as,
                         const float* __restrict__ ad, float* __restrict__ ssrc,
                         float* __restrict__ sdst, int n) {
    int warp = (blockIdx.x * blockDim.x + threadIdx.x) >> 5;
    int lane = threadIdx.x & 31;
    if (warp >= n) return;
    const float* hr = h + (size_t)warp * F_DIM;
    float s1 = 0.f, s2 = 0.f;
#pragma unroll
    for (int j = 0; j < F_DIM / 32; j++) {
        float v = hr[lane + 32 * j];
        s1 += v * as[lane + 32 * j];
        s2 += v * ad[lane + 32 * j];
    }
    for (int o = 16; o; o >>= 1) {
        s1 += __shfl_xor_sync(0xFFFFFFFFu, s1, o);
        s2 += __shfl_xor_sync(0xFFFFFFFFu, s2, o);
    }
    if (lane == 0) { ssrc[warp] = s1; sdst[warp] = s2; }
}

// ---------------- GAT softmax-aggregate (warp per dst node), ELU fused --------
__device__ __forceinline__ float lrelu(float x) { return x > 0.f ? x : 0.2f * x; }

__global__ void k_agg(const float* __restrict__ h, const float* __restrict__ ssrc,
                      const float* __restrict__ sdst, const int* __restrict__ rowptr,
                      const int* __restrict__ srcidx, const float* __restrict__ bias,
                      float* __restrict__ out, int n) {
    int warp = (blockIdx.x * blockDim.x + threadIdx.x) >> 5;
    int lane = threadIdx.x & 31;
    if (warp >= n) return;
    int node = warp;
    float sd = sdst[node];
    int b = rowptr[node], e2 = rowptr[node + 1];
    float eself = lrelu(ssrc[node] + sd);
    float m = eself;
    for (int i = b + lane; i < e2; i += 32)
        m = fmaxf(m, lrelu(ssrc[srcidx[i]] + sd));
    for (int o = 16; o; o >>= 1) m = fmaxf(m, __shfl_xor_sync(0xFFFFFFFFu, m, o));

    float acc[F_DIM / 32];
#pragma unroll
    for (int j = 0; j < F_DIM / 32; j++) acc[j] = 0.f;
    float denom = 0.f;
    for (int i = b; i < e2; i++) {
        int s = srcidx[i];
        float w = expf(lrelu(ssrc[s] + sd) - m);
        denom += w;
        const float* hr = h + (size_t)s * F_DIM;
#pragma unroll
        for (int j = 0; j < F_DIM / 32; j++) acc[j] += w * hr[lane + 32 * j];
    }
    // self-loop
    float ws = expf(eself - m);
    denom += ws;
    const float* hn = h + (size_t)node * F_DIM;
#pragma unroll
    for (int j = 0; j < F_DIM / 32; j++) acc[j] += ws * hn[lane + 32 * j];

    float inv = 1.f / denom;
    float* op = out + (size_t)node * F_DIM;
#pragma unroll
    for (int j = 0; j < F_DIM / 32; j++) {
        float v = acc[j] * inv + bias[lane + 32 * j];
        op[lane + 32 * j] = (v > 0.f) ? v : expm1f(v);   // ELU fused
    }
}

// ---------------- fp32 tiled SGEMM: C[M,N] = A[M,K] @ B[K,N] (+ bias) ---------
#define BM 128
#define BN 64
#define BKK 16

__global__ __launch_bounds__(256) void k_sgemm(const float* __restrict__ A,
                                               const float* __restrict__ B,
                                               const float* __restrict__ bias,
                                               float* __restrict__ C,
                                               int M, int N, int K) {
    __shared__ float As[BKK][BM];
    __shared__ float Bs[BKK][BN];
    int tid = threadIdx.x;
    int tx = tid & 15;   // n-index (4 cols each)
    int ty = tid >> 4;   // m-index (8 rows each)
    int m0 = blockIdx.y * BM;
    int n0 = blockIdx.x * BN;

    float acc[8][4];
#pragma unroll
    for (int i = 0; i < 8; i++)
#pragma unroll
        for (int j = 0; j < 4; j++) acc[i][j] = 0.f;

    int lr  = tid >> 1;          // A tile row
    int lc0 = (tid & 1) * 8;     // A tile col base
    int lk  = tid >> 4;          // B tile row
    int ln  = (tid & 15) * 4;    // B tile col base
    const float* Arow = A + (size_t)(m0 + lr) * K;
    bool arow_ok = (m0 + lr) < M;

    for (int k0 = 0; k0 < K; k0 += BKK) {
#pragma unroll
        for (int j = 0; j < 8; j++) {
            int kc = k0 + lc0 + j;
            As[lc0 + j][lr] = (arow_ok && kc < K) ? Arow[kc] : 0.f;
        }
        {
            int kr = k0 + lk;
            float4 v = make_float4(0.f, 0.f, 0.f, 0.f);
            if (kr < K) v = *(const float4*)&B[(size_t)kr * N + n0 + ln];
            *(float4*)&Bs[lk][ln] = v;
        }
        __syncthreads();
#pragma unroll
        for (int kk = 0; kk < BKK; kk++) {
            float4 a0 = *(const float4*)&As[kk][ty * 8];
            float4 a1 = *(const float4*)&As[kk][ty * 8 + 4];
            float4 bv = *(const float4*)&Bs[kk][tx * 4];
            float a[8] = {a0.x, a0.y, a0.z, a0.w, a1.x, a1.y, a1.z, a1.w};
            float bb[4] = {bv.x, bv.y, bv.z, bv.w};
#pragma unroll
            for (int i = 0; i < 8; i++)
#pragma unroll
                for (int j = 0; j < 4; j++) acc[i][j] += a[i] * bb[j];
        }
        __syncthreads();
    }

    float4 b4 = make_float4(0.f, 0.f, 0.f, 0.f);
    if (bias) b4 = *(const float4*)&bias[n0 + tx * 4];
#pragma unroll
    for (int i = 0; i < 8; i++) {
        int r = m0 + ty * 8 + i;
        if (r < M) {
            float4 o;
            o.x = acc[i][0] + b4.x;
            o.y = acc[i][1] + b4.y;
            o.z = acc[i][2] + b4.z;
            o.w = acc[i][3] + b4.w;
            *(float4*)&C[(size_t)r * N + n0 + tx * 4] = o;
        }
    }
}

// ---------------- BatchNorm (train mode, biased var) + ELU --------------------
__global__ void k_bnstats(const float* __restrict__ x, int M) {
    int col = threadIdx.x;  // 256
    float s = 0.f, q = 0.f;
    for (int r = blockIdx.x; r < M; r += gridDim.x) {
        float v = x[(size_t)r * F_DIM + col];
        s += v;
        q += v * v;
    }
    atomicAdd(&g_sum[col], s);
    atomicAdd(&g_sq[col], q);
}

__global__ void k_bnapply(const float* __restrict__ x, const float* __restrict__ g,
                          const float* __restrict__ be, float* __restrict__ y, int M) {
    int i = blockIdx.x * blockDim.x + threadIdx.x;
    if (i >= M * F_DIM) return;
    int col = i & (F_DIM - 1);
    float invM = 1.f / (float)M;
    float mean = g_sum[col] * invM;
    float var = g_sq[col] * invM - mean * mean;
    float v = (x[i] - mean) * rsqrtf(var + 1e-5f) * g[col] + be[col];
    y[i] = (v > 0.f) ? v : expm1f(v);
}

// ---------------- host: launch pipeline --------------------------------------
extern "C" void kernel_launch(void* const* d_in, const int* in_sizes, int n_in,
                              void* d_out, int out_size) {
    const float* x   = (const float*)d_in[0];
    const int* edges = (const int*)d_in[1];
    const float* W1  = (const float*)d_in[2];
    const float* a1s = (const float*)d_in[3];
    const float* a1d = (const float*)d_in[4];
    const float* b1  = (const float*)d_in[5];
    const float* W2  = (const float*)d_in[6];
    const float* a2s = (const float*)d_in[7];
    const float* a2d = (const float*)d_in[8];
    const float* b2  = (const float*)d_in[9];
    const float* lw1 = (const float*)d_in[10];
    const float* lb1 = (const float*)d_in[11];
    const float* g1  = (const float*)d_in[12];
    const float* be1 = (const float*)d_in[13];
    const float* lw2 = (const float*)d_in[14];
    const float* lb2 = (const float*)d_in[15];
    const float* g2  = (const float*)d_in[16];
    const float* be2 = (const float*)d_in[17];

    int F = in_sizes[3];             // 256
    int D = in_sizes[2] / F;         // 2613
    int Nn = in_sizes[0] / D;        // 50000
    int E = in_sizes[1] / 2;         // 800000
    const int* esrc = edges;
    const int* edst = edges + E;

    float *buf0, *buf1, *ssrc, *sdst;
    int *cnt, *rowptr, *fill, *srcidx, *part;
    cudaGetSymbolAddress((void**)&buf0, g_buf0);
    cudaGetSymbolAddress((void**)&buf1, g_buf1);
    cudaGetSymbolAddress((void**)&ssrc, g_ssrc);
    cudaGetSymbolAddress((void**)&sdst, g_sdst);
    cudaGetSymbolAddress((void**)&cnt, g_cnt);
    cudaGetSymbolAddress((void**)&rowptr, g_rowptr);
    cudaGetSymbolAddress((void**)&fill, g_fill);
    cudaGetSymbolAddress((void**)&srcidx, g_srcidx);
    cudaGetSymbolAddress((void**)&part, g_part);

    int tpb = 256;
    int nwarp_grid = (Nn * 32 + tpb - 1) / tpb;

    // ---- CSR build (group edges by destination) ----
    k_zero_int<<<(Nn + tpb - 1) / tpb, tpb>>>(cnt, Nn);
    k_hist<<<(E + tpb - 1) / tpb, tpb>>>(edst, E, cnt);
    int nb = (Nn + 1023) / 1024;
    k_scan1<<<nb, 1024>>>(cnt, Nn, rowptr, part);
    k_scan2<<<1, 32>>>(part, nb);
    k_scan3<<<(Nn + tpb - 1) / tpb, tpb>>>(rowptr, part, Nn);
    k_copyfill<<<(Nn + tpb - 1) / tpb, tpb>>>(rowptr, fill, Nn);
    k_scatter<<<(E + tpb - 1) / tpb, tpb>>>(esrc, edst, E, fill, srcidx);

    dim3 gdim(F / BN, (Nn + BM - 1) / BM);

    // ---- GAT layer 1 ----
    k_sgemm<<<gdim, 256>>>(x, W1, nullptr, buf0, Nn, F, D);
    k_scores<<<nwarp_grid, tpb>>>(buf0, a1s, a1d, ssrc, sdst, Nn);
    k_agg<<<nwarp_grid, tpb>>>(buf0, ssrc, sdst, rowptr, srcidx, b1, buf1, Nn);

    // ---- GAT layer 2 ----
    k_sgemm<<<gdim, 256>>>(buf1, W2, nullptr, buf0, Nn, F, F);
    k_scores<<<nwarp_grid, tpb>>>(buf0, a2s, a2d, ssrc, sdst, Nn);
    k_agg<<<nwarp_grid, tpb>>>(buf0, ssrc, sdst, rowptr, srcidx, b2, buf1, Nn);

    // ---- Linear1 + BN + ELU ----
    k_sgemm<<<gdim, 256>>>(buf1, lw1, lb1, buf0, Nn, F, F);
    k_zero_stats<<<1, 256>>>();
    k_bnstats<<<256, 256>>>(buf0, Nn);
    k_bnapply<<<(Nn * F + tpb - 1) / tpb, tpb>>>(buf0, g1, be1, buf1, Nn);

    // ---- Linear2 + BN + ELU -> output ----
    k_sgemm<<<gdim, 256>>>(buf1, lw2, lb2, buf0, Nn, F, F);
    k_zero_stats<<<1, 256>>>();
    k_bnstats<<<256, 256>>>(buf0, Nn);
    k_bnapply<<<(Nn * F + tpb - 1) / tpb, tpb>>>(buf0, g2, be2, (float*)d_out, Nn);
}

// round 3
// speedup vs baseline: 1.3014x; 1.3014x over previous
#include <cuda_runtime.h>
#include <cuda_bf16.h>
#include <math.h>
#include <stdint.h>

// Problem-shape constants (registry shapes fixed for this problem id).
#define NN 50000
#define F_DIM 256
#define EE 800000
#define KPAD1 2624            // 2613 padded to multiple of 64

// ---------------- static device scratch (no allocations allowed) -------------
__device__ float g_buf0[NN * F_DIM];   // GEMM outputs
__device__ float g_buf1[NN * F_DIM];   // activations
__device__ float g_ssrc[NN];
__device__ float g_sdst[NN];
__device__ int   g_cnt[NN];
__device__ int   g_rowptr[NN + 1];
__device__ int   g_fill[NN];
__device__ int   g_srcidx[EE];
__device__ int   g_part[64];
__device__ float g_sum[F_DIM];
__device__ float g_sq[F_DIM];
// split-bf16 transposed weights [N=256][Kpad]
__device__ __align__(16) __nv_bfloat16 g_wth[256 * KPAD1];
__device__ __align__(16) __nv_bfloat16 g_wtl[256 * KPAD1];

// ================= warp-MMA helpers (arch-agnostic PTX: sm_80+) ===============
__device__ __forceinline__ uint32_t smem_u32(const void* p) {
    uint32_t a;
    asm("{ .reg .u64 t; cvta.to.shared.u64 t, %1; cvt.u32.u64 %0, t; }"
        : "=r"(a) : "l"(p));
    return a;
}

__device__ __forceinline__ void ldm_x4(uint32_t* r, uint32_t addr) {
    asm volatile("ldmatrix.sync.aligned.m8n8.x4.shared.b16 {%0,%1,%2,%3}, [%4];"
                 : "=r"(r[0]), "=r"(r[1]), "=r"(r[2]), "=r"(r[3]) : "r"(addr));
}

__device__ __forceinline__ void mma16816(float* d, const uint32_t* a, const uint32_t* b) {
    asm volatile(
        "mma.sync.aligned.m16n8k16.row.col.f32.bf16.bf16.f32 "
        "{%0,%1,%2,%3}, {%4,%5,%6,%7}, {%8,%9}, {%0,%1,%2,%3};"
        : "+f"(d[0]), "+f"(d[1]), "+f"(d[2]), "+f"(d[3])
        : "r"(a[0]), "r"(a[1]), "r"(a[2]), "r"(a[3]), "r"(b[0]), "r"(b[1]));
}

// ================= split-bf16 HMMA GEMM =======================================
// C[M,256] = A[M,K] @ W[K,256];  W pre-split/transposed bf16 [256][Kpad] (hi,lo)
// CTA tile 128x128, 8 warps as 4(m) x 2(n), warp tile 32x64, BK=32.
#define BROW 40   // padded SMEM row: 32 bf16 + 8 pad = 80B (conflict-free ldmatrix)

__global__ __launch_bounds__(256, 2) void k_hgemm(
    const float* __restrict__ A, const __nv_bfloat16* __restrict__ Bh,
    const __nv_bfloat16* __restrict__ Bl, const float* __restrict__ bias,
    float* __restrict__ C, int M, int K, int Kpad)
{
    __shared__ __align__(16) __nv_bfloat16 sAh[128][BROW];
    __shared__ __align__(16) __nv_bfloat16 sAl[128][BROW];
    __shared__ __align__(16) __nv_bfloat16 sBh[128][BROW];
    __shared__ __align__(16) __nv_bfloat16 sBl[128][BROW];

    int tid = threadIdx.x;
    int lane = tid & 31, wid = tid >> 5;
    int wm = wid >> 1, wn = wid & 1;          // 4x2 warp grid
    int m0 = blockIdx.y * 128;
    int n0 = blockIdx.x * 128;                 // B rows (n) offset

    float acc[2][8][4];
#pragma unroll
    for (int i = 0; i < 2; i++)
#pragma unroll
        for (int j = 0; j < 8; j++)
#pragma unroll
            for (int q = 0; q < 4; q++) acc[i][j][q] = 0.f;

    uint32_t aAh = smem_u32(sAh), aAl = smem_u32(sAl);
    uint32_t aBh = smem_u32(sBh), aBl = smem_u32(sBl);

    // ldmatrix lane->address decomposition
    int lr = lane & 7;
    int rowA = wm * 32 + lr + ((lane >> 3) & 1) * 8;     // + mf*16
    int colA8 = ((lane >> 4) & 1) * 8;                   // + kb
    int rowB = wn * 64 + lr + ((lane >> 4) & 1) * 8;     // + nf2*16
    int colB8 = ((lane >> 3) & 1) * 8;                   // + kb

    uint32_t offA = (uint32_t)rowA * (BROW * 2);
    uint32_t offB = (uint32_t)rowB * (BROW * 2);

    int NC = Kpad >> 5;
    for (int c = 0; c < NC; c++) {
        int k0 = c << 5;

        // ---- A tile: 128x32 fp32 -> split bf16 hi/lo (pairs) ----
#pragma unroll
        for (int i = 0; i < 8; i++) {
            int idx = (i << 8) + tid;       // 0..2047 pairs
            int r = idx >> 4;               // row
            int kp = idx & 15;              // pair (k = 2*kp)
            int grow = m0 + r, gk = k0 + (kp << 1);
            float v0 = 0.f, v1 = 0.f;
            if (grow < M) {
                const float* ap = A + (size_t)grow * K + gk;
                if (gk < K)     v0 = ap[0];
                if (gk + 1 < K) v1 = ap[1];
            }
            __nv_bfloat16 h0 = __float2bfloat16(v0), h1 = __float2bfloat16(v1);
            __nv_bfloat16 l0 = __float2bfloat16(v0 - __bfloat162float(h0));
            __nv_bfloat16 l1 = __float2bfloat16(v1 - __bfloat162float(h1));
            uint32_t ph = (uint32_t)__bfloat16_as_ushort(h0) | ((uint32_t)__bfloat16_as_ushort(h1) << 16);
            uint32_t pl = (uint32_t)__bfloat16_as_ushort(l0) | ((uint32_t)__bfloat16_as_ushort(l1) << 16);
            *(uint32_t*)&sAh[r][kp << 1] = ph;
            *(uint32_t*)&sAl[r][kp << 1] = pl;
        }

        // ---- B tiles: [n][k] bf16 hi/lo, 128 rows x 64B ----
#pragma unroll
        for (int i = 0; i < 2; i++) {
            int idx = (i << 8) + tid;       // 0..511
            int r = idx >> 2, j = idx & 3;
            size_t gb = (size_t)(n0 + r) * Kpad + k0;
            uint4 vh = *((const uint4*)(Bh + gb) + j);
            uint4 vl = *((const uint4*)(Bl + gb) + j);
            *(uint4*)&sBh[r][j << 3] = vh;
            *(uint4*)&sBl[r][j << 3] = vl;
        }
        __syncthreads();

        // ---- compute: 2 ksteps x (12 ldmatrix.x4 + 48 mma) per warp ----
#pragma unroll
        for (int ks = 0; ks < 2; ks++) {
            int kb = ks << 4;
            uint32_t ah[2][4], al[2][4], bb[8][2];
            uint32_t ca = (uint32_t)((kb + colA8) << 1);
#pragma unroll
            for (int mf = 0; mf < 2; mf++) {
                ldm_x4(ah[mf], aAh + offA + mf * 16 * (BROW * 2) + ca);
                ldm_x4(al[mf], aAl + offA + mf * 16 * (BROW * 2) + ca);
            }
            uint32_t cb = (uint32_t)((kb + colB8) << 1);
#pragma unroll
            for (int nf2 = 0; nf2 < 4; nf2++) {
                uint32_t t4[4];
                ldm_x4(t4, aBh + offB + nf2 * 16 * (BROW * 2) + cb);
                bb[2 * nf2][0] = t4[0]; bb[2 * nf2][1] = t4[1];
                bb[2 * nf2 + 1][0] = t4[2]; bb[2 * nf2 + 1][1] = t4[3];
            }
#pragma unroll
            for (int mf = 0; mf < 2; mf++)
#pragma unroll
                for (int nf = 0; nf < 8; nf++) {
                    mma16816(acc[mf][nf], ah[mf], bb[nf]);   // hi*hi
                }
#pragma unroll
            for (int mf = 0; mf < 2; mf++)
#pragma unroll
                for (int nf = 0; nf < 8; nf++) {
                    mma16816(acc[mf][nf], al[mf], bb[nf]);   // lo*hi
                }
            // reload B_lo into same regs
#pragma unroll
            for (int nf2 = 0; nf2 < 4; nf2++) {
                uint32_t t4[4];
                ldm_x4(t4, aBl + offB + nf2 * 16 * (BROW * 2) + cb);
                bb[2 * nf2][0] = t4[0]; bb[2 * nf2][1] = t4[1];
                bb[2 * nf2 + 1][0] = t4[2]; bb[2 * nf2 + 1][1] = t4[3];
            }
#pragma unroll
            for (int mf = 0; mf < 2; mf++)
#pragma unroll
                for (int nf = 0; nf < 8; nf++) {
                    mma16816(acc[mf][nf], ah[mf], bb[nf]);   // hi*lo
                }
        }
        __syncthreads();
    }

    // ---- epilogue: add bias, store fp32 ----
#pragma unroll
    for (int mf = 0; mf < 2; mf++) {
        int r0 = m0 + wm * 32 + mf * 16 + (lane >> 2);
        int r1 = r0 + 8;
#pragma unroll
        for (int nf = 0; nf < 8; nf++) {
            int cb = n0 + wn * 64 + nf * 8 + (lane & 3) * 2;
            float b0 = 0.f, b1 = 0.f;
            if (bias) { b0 = bias[cb]; b1 = bias[cb + 1]; }
            if (r0 < M) {
                float2 o = make_float2(acc[mf][nf][0] + b0, acc[mf][nf][1] + b1);
                *(float2*)&C[(size_t)r0 * 256 + cb] = o;
            }
            if (r1 < M) {
                float2 o = make_float2(acc[mf][nf][2] + b0, acc[mf][nf][3] + b1);
                *(float2*)&C[(size_t)r1 * 256 + cb] = o;
            }
        }
    }
}

// ---- weight prepass: split fp32 W[K,256] -> transposed bf16 hi/lo [256][Kpad] ----
__global__ void k_splitw(const float* __restrict__ W, int K, int Kpad,
                         __nv_bfloat16* __restrict__ oh, __nv_bfloat16* __restrict__ ol) {
    int idx = blockIdx.x * blockDim.x + threadIdx.x;
    if (idx >= 256 * Kpad) return;
    int n = idx / Kpad, k = idx - n * Kpad;
    float v = (k < K) ? W[(size_t)k * 256 + n] : 0.f;
    __nv_bfloat16 h = __float2bfloat16(v);
    oh[idx] = h;
    ol[idx] = __float2bfloat16(v - __bfloat162float(h));
}

// ---------------- small utility kernels --------------------------------------
__global__ void k_zero_int(int* p, int n) {
    int i = blockIdx.x * blockDim.x + threadIdx.x;
    if (i < n) p[i] = 0;
}

__global__ void k_zero_stats() {
    int i = threadIdx.x;
    if (i < F_DIM) { g_sum[i] = 0.f; g_sq[i] = 0.f; }
}

__global__ void k_hist(const int* __restrict__ dst, int E, int* __restrict__ cnt) {
    int e = blockIdx.x * blockDim.x + threadIdx.x;
    if (e < E) atomicAdd(&cnt[dst[e]], 1);
}

__global__ void k_scan1(const int* __restrict__ cnt, int n, int* __restrict__ rowptr,
                        int* __restrict__ part) {
    __shared__ int s[1024];
    int idx = blockIdx.x * 1024 + threadIdx.x;
    int v = (idx < n) ? cnt[idx] : 0;
    s[threadIdx.x] = v;
    __syncthreads();
    for (int off = 1; off < 1024; off <<= 1) {
        int t = 0;
        if (threadIdx.x >= off) t = s[threadIdx.x - off];
        __syncthreads();
        if (threadIdx.x >= off) s[threadIdx.x] += t;
        __syncthreads();
    }
    if (idx < n) rowptr[idx + 1] = s[threadIdx.x];
    if (threadIdx.x == 1023) part[blockIdx.x] = s[1023];
}

__global__ void k_scan2(int* part, int nb) {
    if (threadIdx.x == 0 && blockIdx.x == 0) {
        int acc = 0;
        for (int i = 0; i < nb; i++) { int v = part[i]; part[i] = acc; acc += v; }
    }
}

__global__ void k_scan3(int* __restrict__ rowptr, const int* __restrict__ part, int n) {
    int idx = blockIdx.x * blockDim.x + threadIdx.x;
    if (idx < n) rowptr[idx + 1] += part[idx >> 10];
    if (idx == 0) rowptr[0] = 0;
}

__global__ void k_copyfill(const int* __restrict__ rowptr, int* __restrict__ fill, int n) {
    int i = blockIdx.x * blockDim.x + threadIdx.x;
    if (i < n) fill[i] = rowptr[i];
}

__global__ void k_scatter(const int* __restrict__ src, const int* __restrict__ dst, int E,
                          int* __restrict__ fill, int* __restrict__ srcidx) {
    int e = blockIdx.x * blockDim.x + threadIdx.x;
    if (e < E) {
        int p = atomicAdd(&fill[dst[e]], 1);
        srcidx[p] = src[e];
    }
}

// ---------------- attention scores (warp per node) ----------------------------
__global__ void k_scores(const float* __restrict__ h, const float* __restrict__ as,
                         const float* __restrict__ ad, float* __restrict__ ssrc,
                         float* __restrict__ sdst, int n) {
    int warp = (blockIdx.x * blockDim.x + threadIdx.x) >> 5;
    int lane = threadIdx.x & 31;
    if (warp >= n) return;
    const float* hr = h + (size_t)warp * F_DIM;
    float s1 = 0.f, s2 = 0.f;
#pragma unroll
    for (int j = 0; j < F_DIM / 32; j++) {
        float v = hr[lane + 32 * j];
        s1 += v * as[lane + 32 * j];
        s2 += v * ad[lane + 32 * j];
    }
    for (int o = 16; o; o >>= 1) {
        s1 += __shfl_xor_sync(0xFFFFFFFFu, s1, o);
        s2 += __shfl_xor_sync(0xFFFFFFFFu, s2, o);
    }
    if (lane == 0) { ssrc[warp] = s1; sdst[warp] = s2; }
}

// ---------------- GAT softmax-aggregate (warp per dst node), ELU fused --------
__device__ __forceinline__ float lrelu(float x) { return x > 0.f ? x : 0.2f * x; }

__global__ void k_agg(const float* __restrict__ h, const float* __restrict__ ssrc,
                      const float* __restrict__ sdst, const int* __restrict__ rowptr,
                      const int* __restrict__ srcidx, const float* __restrict__ bias,
                      float* __restrict__ out, int n) {
    int warp = (blockIdx.x * blockDim.x + threadIdx.x) >> 5;
    int lane = threadIdx.x & 31;
    if (warp >= n) return;
    int node = warp;
    float sd = sdst[node];
    int b = rowptr[node], e2 = rowptr[node + 1];
    float eself = lrelu(ssrc[node] + sd);
    float m = eself;
    for (int i = b + lane; i < e2; i += 32)
        m = fmaxf(m, lrelu(ssrc[srcidx[i]] + sd));
    for (int o = 16; o; o >>= 1) m = fmaxf(m, __shfl_xor_sync(0xFFFFFFFFu, m, o));

    float acc[F_DIM / 32];
#pragma unroll
    for (int j = 0; j < F_DIM / 32; j++) acc[j] = 0.f;
    float denom = 0.f;
    for (int i = b; i < e2; i++) {
        int s = srcidx[i];
        float w = expf(lrelu(ssrc[s] + sd) - m);
        denom += w;
        const float* hr = h + (size_t)s * F_DIM;
#pragma unroll
        for (int j = 0; j < F_DIM / 32; j++) acc[j] += w * hr[lane + 32 * j];
    }
    float ws = expf(eself - m);
    denom += ws;
    const float* hn = h + (size_t)node * F_DIM;
#pragma unroll
    for (int j = 0; j < F_DIM / 32; j++) acc[j] += ws * hn[lane + 32 * j];

    float inv = 1.f / denom;
    float* op = out + (size_t)node * F_DIM;
#pragma unroll
    for (int j = 0; j < F_DIM / 32; j++) {
        float v = acc[j] * inv + bias[lane + 32 * j];
        op[lane + 32 * j] = (v > 0.f) ? v : expm1f(v);   // ELU fused
    }
}

// ---------------- BatchNorm (train mode, biased var) + ELU --------------------
__global__ void k_bnstats(const float* __restrict__ x, int M) {
    int col = threadIdx.x;  // 256
    float s = 0.f, q = 0.f;
    for (int r = blockIdx.x; r < M; r += gridDim.x) {
        float v = x[(size_t)r * F_DIM + col];
        s += v;
        q += v * v;
    }
    atomicAdd(&g_sum[col], s);
    atomicAdd(&g_sq[col], q);
}

__global__ void k_bnapply(const float* __restrict__ x, const float* __restrict__ g,
                          const float* __restrict__ be, float* __restrict__ y, int M) {
    int i = blockIdx.x * blockDim.x + threadIdx.x;
    if (i >= M * F_DIM) return;
    int col = i & (F_DIM - 1);
    float invM = 1.f / (float)M;
    float mean = g_sum[col] * invM;
    float var = g_sq[col] * invM - mean * mean;
    float v = (x[i] - mean) * rsqrtf(var + 1e-5f) * g[col] + be[col];
    y[i] = (v > 0.f) ? v : expm1f(v);
}

// ---------------- host: launch pipeline --------------------------------------
extern "C" void kernel_launch(void* const* d_in, const int* in_sizes, int n_in,
                              void* d_out, int out_size) {
    const float* x   = (const float*)d_in[0];
    const int* edges = (const int*)d_in[1];
    const float* W1  = (const float*)d_in[2];
    const float* a1s = (const float*)d_in[3];
    const float* a1d = (const float*)d_in[4];
    const float* b1  = (const float*)d_in[5];
    const float* W2  = (const float*)d_in[6];
    const float* a2s = (const float*)d_in[7];
    const float* a2d = (const float*)d_in[8];
    const float* b2  = (const float*)d_in[9];
    const float* lw1 = (const float*)d_in[10];
    const float* lb1 = (const float*)d_in[11];
    const float* g1  = (const float*)d_in[12];
    const float* be1 = (const float*)d_in[13];
    const float* lw2 = (const float*)d_in[14];
    const float* lb2 = (const float*)d_in[15];
    const float* g2  = (const float*)d_in[16];
    const float* be2 = (const float*)d_in[17];

    int F = in_sizes[3];             // 256
    int D = in_sizes[2] / F;         // 2613
    int Nn = in_sizes[0] / D;        // 50000
    int E = in_sizes[1] / 2;         // 800000
    const int* esrc = edges;
    const int* edst = edges + E;
    int Dpad = (D + 63) & ~63;       // 2624

    float *buf0, *buf1, *ssrc, *sdst;
    int *cnt, *rowptr, *fill, *srcidx, *part;
    __nv_bfloat16 *wth, *wtl;
    cudaGetSymbolAddress((void**)&buf0, g_buf0);
    cudaGetSymbolAddress((void**)&buf1, g_buf1);
    cudaGetSymbolAddress((void**)&ssrc, g_ssrc);
    cudaGetSymbolAddress((void**)&sdst, g_sdst);
    cudaGetSymbolAddress((void**)&cnt, g_cnt);
    cudaGetSymbolAddress((void**)&rowptr, g_rowptr);
    cudaGetSymbolAddress((void**)&fill, g_fill);
    cudaGetSymbolAddress((void**)&srcidx, g_srcidx);
    cudaGetSymbolAddress((void**)&part, g_part);
    cudaGetSymbolAddress((void**)&wth, g_wth);
    cudaGetSymbolAddress((void**)&wtl, g_wtl);

    int tpb = 256;
    int nwarp_grid = (Nn * 32 + tpb - 1) / tpb;
    dim3 ggrid(2, (Nn + 127) / 128);

    // ---- CSR build (group edges by destination) ----
    k_zero_int<<<(Nn + tpb - 1) / tpb, tpb>>>(cnt, Nn);
    k_hist<<<(E + tpb - 1) / tpb, tpb>>>(edst, E, cnt);
    int nb = (Nn + 1023) / 1024;
    k_scan1<<<nb, 1024>>>(cnt, Nn, rowptr, part);
    k_scan2<<<1, 32>>>(part, nb);
    k_scan3<<<(Nn + tpb - 1) / tpb, tpb>>>(rowptr, part, Nn);
    k_copyfill<<<(Nn + tpb - 1) / tpb, tpb>>>(rowptr, fill, Nn);
    k_scatter<<<(E + tpb - 1) / tpb, tpb>>>(esrc, edst, E, fill, srcidx);

    // ---- GAT layer 1 ----
    k_splitw<<<(256 * Dpad + tpb - 1) / tpb, tpb>>>(W1, D, Dpad, wth, wtl);
    k_hgemm<<<ggrid, 256>>>(x, wth, wtl, nullptr, buf0, Nn, D, Dpad);
    k_scores<<<nwarp_grid, tpb>>>(buf0, a1s, a1d, ssrc, sdst, Nn);
    k_agg<<<nwarp_grid, tpb>>>(buf0, ssrc, sdst, rowptr, srcidx, b1, buf1, Nn);

    // ---- GAT layer 2 ----
    k_splitw<<<(256 * 256 + tpb - 1) / tpb, tpb>>>(W2, F, F, wth, wtl);
    k_hgemm<<<ggrid, 256>>>(buf1, wth, wtl, nullptr, buf0, Nn, F, F);
    k_scores<<<nwarp_grid, tpb>>>(buf0, a2s, a2d, ssrc, sdst, Nn);
    k_agg<<<nwarp_grid, tpb>>>(buf0, ssrc, sdst, rowptr, srcidx, b2, buf1, Nn);

    // ---- Linear1 + BN + ELU ----
    k_splitw<<<(256 * 256 + tpb - 1) / tpb, tpb>>>(lw1, F, F, wth, wtl);
    k_hgemm<<<ggrid, 256>>>(buf1, wth, wtl, lb1, buf0, Nn, F, F);
    k_zero_stats<<<1, 256>>>();
    k_bnstats<<<256, 256>>>(buf0, Nn);
    k_bnapply<<<(Nn * F + tpb - 1) / tpb, tpb>>>(buf0, g1, be1, buf1, Nn);

    // ---- Linear2 + BN + ELU -> output ----
    k_splitw<<<(256 * 256 + tpb - 1) / tpb, tpb>>>(lw2, F, F, wth, wtl);
    k_hgemm<<<ggrid, 256>>>(buf1, wth, wtl, lb2, buf0, Nn, F, F);
    k_zero_stats<<<1, 256>>>();
    k_bnstats<<<256, 256>>>(buf0, Nn);
    k_bnapply<<<(Nn * F + tpb - 1) / tpb, tpb>>>(buf0, g2, be2, (float*)d_out, Nn);
}

// round 4
// speedup vs baseline: 2.2844x; 1.7554x over previous
#include <cuda_runtime.h>
#include <cuda_bf16.h>
#include <math.h>
#include <stdint.h>

// Problem-shape constants (registry shapes fixed for this problem id).
#define NN 50000
#define F_DIM 256
#define EE 800000
#define KPAD1 2624            // 2613 padded to multiple of 64

// ---------------- static device scratch (no allocations allowed) -------------
__device__ float g_buf0[NN * F_DIM];   // GEMM outputs
__device__ float g_buf1[NN * F_DIM];   // activations
__device__ float g_ssrc[NN];
__device__ float g_sdst[NN];
__device__ int   g_cnt[NN];
__device__ int   g_rowptr[NN + 1];
__device__ int   g_fill[NN];
__device__ int   g_srcidx[EE];
__device__ int   g_part[64];
__device__ float g_sum[F_DIM];
__device__ float g_sq[F_DIM];
// split-bf16 transposed weights [N=256][Kpad]
__device__ __align__(16) __nv_bfloat16 g_wth[256 * KPAD1];
__device__ __align__(16) __nv_bfloat16 g_wtl[256 * KPAD1];

// ================= warp-MMA helpers (arch-agnostic PTX: sm_80+) ===============
__device__ __forceinline__ uint32_t smem_u32(const void* p) {
    uint32_t a;
    asm("{ .reg .u64 t; cvta.to.shared.u64 t, %1; cvt.u32.u64 %0, t; }"
        : "=r"(a) : "l"(p));
    return a;
}

__device__ __forceinline__ void ldm_x4(uint32_t* r, uint32_t addr) {
    asm volatile("ldmatrix.sync.aligned.m8n8.x4.shared.b16 {%0,%1,%2,%3}, [%4];"
                 : "=r"(r[0]), "=r"(r[1]), "=r"(r[2]), "=r"(r[3]) : "r"(addr));
}

__device__ __forceinline__ void mma16816(float* d, const uint32_t* a, const uint32_t* b) {
    asm volatile(
        "mma.sync.aligned.m16n8k16.row.col.f32.bf16.bf16.f32 "
        "{%0,%1,%2,%3}, {%4,%5,%6,%7}, {%8,%9}, {%0,%1,%2,%3};"
        : "+f"(d[0]), "+f"(d[1]), "+f"(d[2]), "+f"(d[3])
        : "r"(a[0]), "r"(a[1]), "r"(a[2]), "r"(a[3]), "r"(b[0]), "r"(b[1]));
}

__device__ __forceinline__ void cp16(uint32_t dst, const void* src) {
    asm volatile("cp.async.cg.shared.global [%0], [%1], 16;" :: "r"(dst), "l"(src));
}
#define CP_COMMIT() asm volatile("cp.async.commit_group;" ::: "memory")
#define CP_WAIT0()  asm volatile("cp.async.wait_group 0;" ::: "memory")

// ================= split-bf16 HMMA GEMM (pipelined) ===========================
// C[M,256] = A[M,K] @ W[K,256];  W pre-split/transposed bf16 [256][Kpad] (hi,lo)
// CTA tile 128x128, 8 warps 4(m)x2(n), warp tile 32x64, BK=32, 2-stage pipeline.
#define BROWB 80           // padded SMEM row bytes: 32 bf16 + 8 pad
#define OFF_AH 0
#define OFF_AL 10240
#define OFF_BH 20480
#define OFF_BL 30720
#define STG_STRIDE 40960
#define GSM_TOTAL (2 * STG_STRIDE)

__global__ __launch_bounds__(256, 2) void k_hgemm(
    const float* __restrict__ A, const __nv_bfloat16* __restrict__ Bh,
    const __nv_bfloat16* __restrict__ Bl, const float* __restrict__ bias,
    float* __restrict__ C, int M, int K, int Kpad)
{
    extern __shared__ __align__(16) char dsm[];
    uint32_t sbase = smem_u32(dsm);

    int tid = threadIdx.x;
    int lane = tid & 31, wid = tid >> 5;
    int wm = wid >> 1, wn = wid & 1;          // 4x2 warp grid
    int m0 = blockIdx.y * 128;
    int n0 = blockIdx.x * 128;

    float acc[2][8][4];
#pragma unroll
    for (int i = 0; i < 2; i++)
#pragma unroll
        for (int j = 0; j < 8; j++)
#pragma unroll
            for (int q = 0; q < 4; q++) acc[i][j][q] = 0.f;

    // ldmatrix lane->address decomposition
    int lr = lane & 7;
    int rowA = wm * 32 + lr + ((lane >> 3) & 1) * 8;
    int colA8 = ((lane >> 4) & 1) * 8;
    int rowB = wn * 64 + lr + ((lane >> 4) & 1) * 8;
    int colB8 = ((lane >> 3) & 1) * 8;
    uint32_t offA = (uint32_t)rowA * BROWB;
    uint32_t offB = (uint32_t)rowB * BROWB;

    // A-register prefetch decomposition: thread covers 8 (row, kpair) slots
    int ar = tid >> 4;            // base row (stride 16 rows per i)  -> r = ar + 16? no:
    // idx = i*256 + tid ; r = idx>>4 = i*16 + (tid>>4); kp = tid & 15
    int akp = tid & 15;

    float areg[16];

    int NC = Kpad >> 5;

    // ---- prologue: A regs chunk0, cp.async B chunk0 ----
    {
        int k0 = 0;
#pragma unroll
        for (int i = 0; i < 8; i++) {
            int r = i * 16 + ar;
            int grow = m0 + r, gk = k0 + (akp << 1);
            float v0 = 0.f, v1 = 0.f;
            if (grow < M) {
                const float* ap = A + (size_t)grow * K;
                if (gk < K)     v0 = ap[gk];
                if (gk + 1 < K) v1 = ap[gk + 1];
            }
            areg[2 * i] = v0; areg[2 * i + 1] = v1;
        }
#pragma unroll
        for (int i = 0; i < 4; i++) {
            int idx = (i << 8) + tid;
            int hl = idx >> 9;
            int rem = idx & 511;
            int r = rem >> 2, j = rem & 3;
            const __nv_bfloat16* src = (hl ? Bl : Bh) + (size_t)(n0 + r) * Kpad + k0 + (j << 3);
            uint32_t dst = sbase + (hl ? OFF_BL : OFF_BH) + r * BROWB + (j << 4);
            cp16(dst, src);
        }
        CP_COMMIT();
    }

    for (int c = 0; c < NC; c++) {
        int st = c & 1;
        uint32_t stOff = (uint32_t)st * STG_STRIDE;

        // ---- convert prefetched A regs -> bf16 hi/lo in SMEM stage st ----
#pragma unroll
        for (int i = 0; i < 8; i++) {
            int r = i * 16 + ar;
            float v0 = areg[2 * i], v1 = areg[2 * i + 1];
            __nv_bfloat16 h0 = __float2bfloat16(v0), h1 = __float2bfloat16(v1);
            __nv_bfloat16 l0 = __float2bfloat16(v0 - __bfloat162float(h0));
            __nv_bfloat16 l1 = __float2bfloat16(v1 - __bfloat162float(h1));
            uint32_t ph = (uint32_t)__bfloat16_as_ushort(h0) | ((uint32_t)__bfloat16_as_ushort(h1) << 16);
            uint32_t pl = (uint32_t)__bfloat16_as_ushort(l0) | ((uint32_t)__bfloat16_as_ushort(l1) << 16);
            uint32_t rowoff = (uint32_t)r * BROWB + ((uint32_t)akp << 2);
            *(uint32_t*)(dsm + stOff + OFF_AH + rowoff) = ph;
            *(uint32_t*)(dsm + stOff + OFF_AL + rowoff) = pl;
        }

        CP_WAIT0();            // B(c) arrived
        __syncthreads();       // converts + B visible to all

        // ---- issue next chunk's loads (overlap with compute) ----
        if (c + 1 < NC) {
            int k0n = (c + 1) << 5;
            uint32_t stN = (uint32_t)((c + 1) & 1) * STG_STRIDE;
#pragma unroll
            for (int i = 0; i < 4; i++) {
                int idx = (i << 8) + tid;
                int hl = idx >> 9;
                int rem = idx & 511;
                int r = rem >> 2, j = rem & 3;
                const __nv_bfloat16* src = (hl ? Bl : Bh) + (size_t)(n0 + r) * Kpad + k0n + (j << 3);
                uint32_t dst = sbase + stN + (hl ? OFF_BL : OFF_BH) + r * BROWB + (j << 4);
                cp16(dst, src);
            }
            CP_COMMIT();
#pragma unroll
            for (int i = 0; i < 8; i++) {
                int r = i * 16 + ar;
                int grow = m0 + r, gk = k0n + (akp << 1);
                float v0 = 0.f, v1 = 0.f;
                if (grow < M) {
                    const float* ap = A + (size_t)grow * K;
                    if (gk < K)     v0 = ap[gk];
                    if (gk + 1 < K) v1 = ap[gk + 1];
                }
                areg[2 * i] = v0; areg[2 * i + 1] = v1;
            }
        }

        // ---- compute chunk c ----
        uint32_t bAh = sbase + stOff + OFF_AH;
        uint32_t bAl = sbase + stOff + OFF_AL;
        uint32_t bBh = sbase + stOff + OFF_BH;
        uint32_t bBl = sbase + stOff + OFF_BL;
#pragma unroll
        for (int ks = 0; ks < 2; ks++) {
            int kb = ks << 4;
            uint32_t ah[2][4], al[2][4], bb[8][2];
            uint32_t ca = (uint32_t)((kb + colA8) << 1);
#pragma unroll
            for (int mf = 0; mf < 2; mf++) {
                ldm_x4(ah[mf], bAh + offA + mf * 16 * BROWB + ca);
                ldm_x4(al[mf], bAl + offA + mf * 16 * BROWB + ca);
            }
            uint32_t cb = (uint32_t)((kb + colB8) << 1);
#pragma unroll
            for (int nf2 = 0; nf2 < 4; nf2++) {
                uint32_t t4[4];
                ldm_x4(t4, bBh + offB + nf2 * 16 * BROWB + cb);
                bb[2 * nf2][0] = t4[0]; bb[2 * nf2][1] = t4[1];
                bb[2 * nf2 + 1][0] = t4[2]; bb[2 * nf2 + 1][1] = t4[3];
            }
#pragma unroll
            for (int mf = 0; mf < 2; mf++)
#pragma unroll
                for (int nf = 0; nf < 8; nf++) mma16816(acc[mf][nf], ah[mf], bb[nf]);
#pragma unroll
            for (int mf = 0; mf < 2; mf++)
#pragma unroll
                for (int nf = 0; nf < 8; nf++) mma16816(acc[mf][nf], al[mf], bb[nf]);
#pragma unroll
            for (int nf2 = 0; nf2 < 4; nf2++) {
                uint32_t t4[4];
                ldm_x4(t4, bBl + offB + nf2 * 16 * BROWB + cb);
                bb[2 * nf2][0] = t4[0]; bb[2 * nf2][1] = t4[1];
                bb[2 * nf2 + 1][0] = t4[2]; bb[2 * nf2 + 1][1] = t4[3];
            }
#pragma unroll
            for (int mf = 0; mf < 2; mf++)
#pragma unroll
                for (int nf = 0; nf < 8; nf++) mma16816(acc[mf][nf], ah[mf], bb[nf]);
        }
        __syncthreads();
    }

    // ---- epilogue: add bias, store fp32 ----
#pragma unroll
    for (int mf = 0; mf < 2; mf++) {
        int r0 = m0 + wm * 32 + mf * 16 + (lane >> 2);
        int r1 = r0 + 8;
#pragma unroll
        for (int nf = 0; nf < 8; nf++) {
            int cb = n0 + wn * 64 + nf * 8 + (lane & 3) * 2;
            float b0 = 0.f, b1 = 0.f;
            if (bias) { b0 = bias[cb]; b1 = bias[cb + 1]; }
            if (r0 < M) {
                float2 o = make_float2(acc[mf][nf][0] + b0, acc[mf][nf][1] + b1);
                *(float2*)&C[(size_t)r0 * 256 + cb] = o;
            }
            if (r1 < M) {
                float2 o = make_float2(acc[mf][nf][2] + b0, acc[mf][nf][3] + b1);
                *(float2*)&C[(size_t)r1 * 256 + cb] = o;
            }
        }
    }
}

// ---- weight prepass: split fp32 W[K,256] -> transposed bf16 hi/lo [256][Kpad] ----
__global__ void k_splitw(const float* __restrict__ W, int K, int Kpad,
                         __nv_bfloat16* __restrict__ oh, __nv_bfloat16* __restrict__ ol) {
    int idx = blockIdx.x * blockDim.x + threadIdx.x;
    if (idx >= 256 * Kpad) return;
    int n = idx / Kpad, k = idx - n * Kpad;
    float v = (k < K) ? W[(size_t)k * 256 + n] : 0.f;
    __nv_bfloat16 h = __float2bfloat16(v);
    oh[idx] = h;
    ol[idx] = __float2bfloat16(v - __bfloat162float(h));
}

// ---------------- small utility kernels --------------------------------------
__global__ void k_zero_int(int* p, int n) {
    int i = blockIdx.x * blockDim.x + threadIdx.x;
    if (i < n) p[i] = 0;
}

__global__ void k_zero_stats() {
    int i = threadIdx.x;
    if (i < F_DIM) { g_sum[i] = 0.f; g_sq[i] = 0.f; }
}

__global__ void k_hist(const int* __restrict__ dst, int E, int* __restrict__ cnt) {
    int e = blockIdx.x * blockDim.x + threadIdx.x;
    if (e < E) atomicAdd(&cnt[dst[e]], 1);
}

__global__ void k_scan1(const int* __restrict__ cnt, int n, int* __restrict__ rowptr,
                        int* __restrict__ part) {
    __shared__ int s[1024];
    int idx = blockIdx.x * 1024 + threadIdx.x;
    int v = (idx < n) ? cnt[idx] : 0;
    s[threadIdx.x] = v;
    __syncthreads();
    for (int off = 1; off < 1024; off <<= 1) {
        int t = 0;
        if (threadIdx.x >= off) t = s[threadIdx.x - off];
        __syncthreads();
        if (threadIdx.x >= off) s[threadIdx.x] += t;
        __syncthreads();
    }
    if (idx < n) rowptr[idx + 1] = s[threadIdx.x];
    if (threadIdx.x == 1023) part[blockIdx.x] = s[1023];
}

__global__ void k_scan2(int* part, int nb) {
    if (threadIdx.x == 0 && blockIdx.x == 0) {
        int acc = 0;
        for (int i = 0; i < nb; i++) { int v = part[i]; part[i] = acc; acc += v; }
    }
}

__global__ void k_scan3(int* __restrict__ rowptr, const int* __restrict__ part, int n) {
    int idx = blockIdx.x * blockDim.x + threadIdx.x;
    if (idx < n) rowptr[idx + 1] += part[idx >> 10];
    if (idx == 0) rowptr[0] = 0;
}

__global__ void k_copyfill(const int* __restrict__ rowptr, int* __restrict__ fill, int n) {
    int i = blockIdx.x * blockDim.x + threadIdx.x;
    if (i < n) fill[i] = rowptr[i];
}

__global__ void k_scatter(const int* __restrict__ src, const int* __restrict__ dst, int E,
                          int* __restrict__ fill, int* __restrict__ srcidx) {
    int e = blockIdx.x * blockDim.x + threadIdx.x;
    if (e < E) {
        int p = atomicAdd(&fill[dst[e]], 1);
        srcidx[p] = src[e];
    }
}

// ---------------- attention scores (warp per node) ----------------------------
__global__ void k_scores(const float* __restrict__ h, const float* __restrict__ as,
                         const float* __restrict__ ad, float* __restrict__ ssrc,
                         float* __restrict__ sdst, int n) {
    int warp = (blockIdx.x * blockDim.x + threadIdx.x) >> 5;
    int lane = threadIdx.x & 31;
    if (warp >= n) return;
    const float* hr = h + (size_t)warp * F_DIM;
    float s1 = 0.f, s2 = 0.f;
#pragma unroll
    for (int j = 0; j < F_DIM / 32; j++) {
        float v = hr[lane + 32 * j];
        s1 += v * as[lane + 32 * j];
        s2 += v * ad[lane + 32 * j];
    }
    for (int o = 16; o; o >>= 1) {
        s1 += __shfl_xor_sync(0xFFFFFFFFu, s1, o);
        s2 += __shfl_xor_sync(0xFFFFFFFFu, s2, o);
    }
    if (lane == 0) { ssrc[warp] = s1; sdst[warp] = s2; }
}

// ---------------- GAT softmax-aggregate (warp per dst node), ELU fused --------
__device__ __forceinline__ float lrelu(float x) { return x > 0.f ? x : 0.2f * x; }

__global__ void k_agg(const float* __restrict__ h, const float* __restrict__ ssrc,
                      const float* __restrict__ sdst, const int* __restrict__ rowptr,
                      const int* __restrict__ srcidx, const float* __restrict__ bias,
                      float* __restrict__ out, int n) {
    int warp = (blockIdx.x * blockDim.x + threadIdx.x) >> 5;
    int lane = threadIdx.x & 31;
    if (warp >= n) return;
    int node = warp;
    float sd = sdst[node];
    int b = rowptr[node], e2 = rowptr[node + 1];
    float eself = lrelu(ssrc[node] + sd);
    float m = eself;
    for (int i = b + lane; i < e2; i += 32)
        m = fmaxf(m, lrelu(ssrc[srcidx[i]] + sd));
    for (int o = 16; o; o >>= 1) m = fmaxf(m, __shfl_xor_sync(0xFFFFFFFFu, m, o));

    float acc[F_DIM / 32];
#pragma unroll
    for (int j = 0; j < F_DIM / 32; j++) acc[j] = 0.f;
    float denom = 0.f;
    for (int i = b; i < e2; i++) {
        int s = srcidx[i];
        float w = expf(lrelu(ssrc[s] + sd) - m);
        denom += w;
        const float* hr = h + (size_t)s * F_DIM;
#pragma unroll
        for (int j = 0; j < F_DIM / 32; j++) acc[j] += w * hr[lane + 32 * j];
    }
    float ws = expf(eself - m);
    denom += ws;
    const float* hn = h + (size_t)node * F_DIM;
#pragma unroll
    for (int j = 0; j < F_DIM / 32; j++) acc[j] += ws * hn[lane + 32 * j];

    float inv = 1.f / denom;
    float* op = out + (size_t)node * F_DIM;
#pragma unroll
    for (int j = 0; j < F_DIM / 32; j++) {
        float v = acc[j] * inv + bias[lane + 32 * j];
        op[lane + 32 * j] = (v > 0.f) ? v : expm1f(v);   // ELU fused
    }
}

// ---------------- BatchNorm (train mode, biased var) + ELU --------------------
__global__ void k_bnstats(const float* __restrict__ x, int M) {
    int col = threadIdx.x;  // 256
    float s = 0.f, q = 0.f;
    for (int r = blockIdx.x; r < M; r += gridDim.x) {
        float v = x[(size_t)r * F_DIM + col];
        s += v;
        q += v * v;
    }
    atomicAdd(&g_sum[col], s);
    atomicAdd(&g_sq[col], q);
}

__global__ void k_bnapply(const float* __restrict__ x, const float* __restrict__ g,
                          const float* __restrict__ be, float* __restrict__ y, int M) {
    int i = blockIdx.x * blockDim.x + threadIdx.x;
    if (i >= M * F_DIM) return;
    int col = i & (F_DIM - 1);
    float invM = 1.f / (float)M;
    float mean = g_sum[col] * invM;
    float var = g_sq[col] * invM - mean * mean;
    float v = (x[i] - mean) * rsqrtf(var + 1e-5f) * g[col] + be[col];
    y[i] = (v > 0.f) ? v : expm1f(v);
}

// ---------------- host: launch pipeline --------------------------------------
extern "C" void kernel_launch(void* const* d_in, const int* in_sizes, int n_in,
                              void* d_out, int out_size) {
    const float* x   = (const float*)d_in[0];
    const int* edges = (const int*)d_in[1];
    const float* W1  = (const float*)d_in[2];
    const float* a1s = (const float*)d_in[3];
    const float* a1d = (const float*)d_in[4];
    const float* b1  = (const float*)d_in[5];
    const float* W2  = (const float*)d_in[6];
    const float* a2s = (const float*)d_in[7];
    const float* a2d = (const float*)d_in[8];
    const float* b2  = (const float*)d_in[9];
    const float* lw1 = (const float*)d_in[10];
    const float* lb1 = (const float*)d_in[11];
    const float* g1  = (const float*)d_in[12];
    const float* be1 = (const float*)d_in[13];
    const float* lw2 = (const float*)d_in[14];
    const float* lb2 = (const float*)d_in[15];
    const float* g2  = (const float*)d_in[16];
    const float* be2 = (const float*)d_in[17];

    int F = in_sizes[3];             // 256
    int D = in_sizes[2] / F;         // 2613
    int Nn = in_sizes[0] / D;        // 50000
    int E = in_sizes[1] / 2;         // 800000
    const int* esrc = edges;
    const int* edst = edges + E;
    int Dpad = (D + 63) & ~63;       // 2624

    float *buf0, *buf1, *ssrc, *sdst;
    int *cnt, *rowptr, *fill, *srcidx, *part;
    __nv_bfloat16 *wth, *wtl;
    cudaGetSymbolAddress((void**)&buf0, g_buf0);
    cudaGetSymbolAddress((void**)&buf1, g_buf1);
    cudaGetSymbolAddress((void**)&ssrc, g_ssrc);
    cudaGetSymbolAddress((void**)&sdst, g_sdst);
    cudaGetSymbolAddress((void**)&cnt, g_cnt);
    cudaGetSymbolAddress((void**)&rowptr, g_rowptr);
    cudaGetSymbolAddress((void**)&fill, g_fill);
    cudaGetSymbolAddress((void**)&srcidx, g_srcidx);
    cudaGetSymbolAddress((void**)&part, g_part);
    cudaGetSymbolAddress((void**)&wth, g_wth);
    cudaGetSymbolAddress((void**)&wtl, g_wtl);

    cudaFuncSetAttribute(k_hgemm, cudaFuncAttributeMaxDynamicSharedMemorySize, GSM_TOTAL);

    int tpb = 256;
    int nwarp_grid = (Nn * 32 + tpb - 1) / tpb;
    dim3 ggrid(2, (Nn + 127) / 128);

    // Launch order arranged so ncu (-s 5 -c 1) captures the big GEMM (launch #6).
    k_splitw<<<(256 * Dpad + tpb - 1) / tpb, tpb>>>(W1, D, Dpad, wth, wtl);       // 1
    k_zero_int<<<(Nn + tpb - 1) / tpb, tpb>>>(cnt, Nn);                           // 2
    k_hist<<<(E + tpb - 1) / tpb, tpb>>>(edst, E, cnt);                           // 3
    int nb = (Nn + 1023) / 1024;
    k_scan1<<<nb, 1024>>>(cnt, Nn, rowptr, part);                                 // 4
    k_scan2<<<1, 32>>>(part, nb);                                                 // 5
    k_hgemm<<<ggrid, 256, GSM_TOTAL>>>(x, wth, wtl, nullptr, buf0, Nn, D, Dpad);  // 6 <- ncu
    k_scan3<<<(Nn + tpb - 1) / tpb, tpb>>>(rowptr, part, Nn);                     // 7
    k_copyfill<<<(Nn + tpb - 1) / tpb, tpb>>>(rowptr, fill, Nn);                  // 8
    k_scatter<<<(E + tpb - 1) / tpb, tpb>>>(esrc, edst, E, fill, srcidx);         // 9

    // ---- GAT layer 1 (scores/agg) ----
    k_scores<<<nwarp_grid, tpb>>>(buf0, a1s, a1d, ssrc, sdst, Nn);
    k_agg<<<nwarp_grid, tpb>>>(buf0, ssrc, sdst, rowptr, srcidx, b1, buf1, Nn);

    // ---- GAT layer 2 ----
    k_splitw<<<(256 * 256 + tpb - 1) / tpb, tpb>>>(W2, F, F, wth, wtl);
    k_hgemm<<<ggrid, 256, GSM_TOTAL>>>(buf1, wth, wtl, nullptr, buf0, Nn, F, F);
    k_scores<<<nwarp_grid, tpb>>>(buf0, a2s, a2d, ssrc, sdst, Nn);
    k_agg<<<nwarp_grid, tpb>>>(buf0, ssrc, sdst, rowptr, srcidx, b2, buf1, Nn);

    // ---- Linear1 + BN + ELU ----
    k_splitw<<<(256 * 256 + tpb - 1) / tpb, tpb>>>(lw1, F, F, wth, wtl);
    k_hgemm<<<ggrid, 256, GSM_TOTAL>>>(buf1, wth, wtl, lb1, buf0, Nn, F, F);
    k_zero_stats<<<1, 256>>>();
    k_bnstats<<<256, 256>>>(buf0, Nn);
    k_bnapply<<<(Nn * F + tpb - 1) / tpb, tpb>>>(buf0, g1, be1, buf1, Nn);

    // ---- Linear2 + BN + ELU -> output ----
    k_splitw<<<(256 * 256 + tpb - 1) / tpb, tpb>>>(lw2, F, F, wth, wtl);
    k_hgemm<<<ggrid, 256, GSM_TOTAL>>>(buf1, wth, wtl, lb2, buf0, Nn, F, F);
    k_zero_stats<<<1, 256>>>();
    k_bnstats<<<256, 256>>>(buf0, Nn);
    k_bnapply<<<(Nn * F + tpb - 1) / tpb, tpb>>>(buf0, g2, be2, (float*)d_out, Nn);
}